// round 1
// baseline (speedup 1.0000x reference)
#include <cuda_runtime.h>
#include <math_constants.h>
#include <cstdint>

#define D     256
#define NROWS 32768
#define KCB   4096
#define BM    128
#define BN    128
#define ZPAD  132                 // row stride (floats) for smem tiles, 528B = 16B-aligned
#define SM_Z  (D * ZPAD)          // 33792 floats
#define SM_E  (8 * ZPAD)          // 1056 floats per buffer
#define SMEM_BYTES ((SM_Z + 2 * SM_E) * 4)   // 143616 B

// Scratch (device globals: no allocations allowed in kernel_launch)
__device__ float  g_zsq[NROWS];
__device__ float  g_esq[KCB];
__device__ int    g_idx[NROWS];
__device__ double g_loss;

// ---------------------------------------------------------------------------
// Kernel 1: row norms ||z||^2 (N rows) and ||e||^2 (K rows), zero loss accum.
// One warp per row; reduction order is irrelevant (whole-ulp invariance of z^2,
// and e^2 is fully absorbed by the fp32 rounding of z^2 + e^2).
// ---------------------------------------------------------------------------
__global__ void vq_prep(const float* __restrict__ x, const float* __restrict__ cb)
{
    if (blockIdx.x == 0 && threadIdx.x == 0) g_loss = 0.0;
    const int warp  = (blockIdx.x * blockDim.x + threadIdx.x) >> 5;
    const int lane  = threadIdx.x & 31;
    const int nwarp = (gridDim.x * blockDim.x) >> 5;
    for (int r = warp; r < NROWS + KCB; r += nwarp) {
        const float* src = (r < NROWS) ? (x + (size_t)r * D)
                                       : (cb + (size_t)(r - NROWS) * D);
        float s = 0.f;
#pragma unroll
        for (int i = 0; i < 2; i++) {
            float4 v = *(const float4*)(src + lane * 8 + i * 4);
            s = fmaf(v.x, v.x, s); s = fmaf(v.y, v.y, s);
            s = fmaf(v.z, v.z, s); s = fmaf(v.w, v.w, s);
        }
#pragma unroll
        for (int off = 16; off; off >>= 1) s += __shfl_xor_sync(0xffffffffu, s, off);
        if (lane == 0) { if (r < NROWS) g_zsq[r] = s; else g_esq[r - NROWS] = s; }
    }
}

// ---------------------------------------------------------------------------
// Kernel 2: fused distance-GEMM + argmin.
// Block = 128 rows of z (persistent in smem, d-major) x full K loop.
// Per K-tile of 128 codebook entries: stream D in chunks of 8 (double-buffered),
// 8x8 register tile per thread, then fold distances into the running argmin.
// Distance exactly mirrors the reference rounding:
//   t = fl(z_sq + e_sq);  dist = fl(t - 2*acc)  (2*acc exact; FMA rounds once)
// ---------------------------------------------------------------------------
__global__ void __launch_bounds__(256, 1)
vq_main(const float* __restrict__ x, const float* __restrict__ cb,
        float* __restrict__ out_idxf, int write_idxf)
{
    extern __shared__ float sm[];
    float* zs = sm;           // [D][ZPAD]
    float* es = sm + SM_Z;    // [2][8][ZPAD]

    const int tid  = threadIdx.x;
    const int tx   = tid & 15;
    const int ty   = tid >> 4;
    const int row0 = blockIdx.x * BM;

    // Load z tile, transposed to d-major
    for (int i = tid; i < BM * (D / 4); i += 256) {
        int r  = i >> 6;             // 0..127
        int d4 = (i & 63) << 2;      // 0,4,...,252
        float4 v = *(const float4*)(x + (size_t)(row0 + r) * D + d4);
        zs[(d4 + 0) * ZPAD + r] = v.x;
        zs[(d4 + 1) * ZPAD + r] = v.y;
        zs[(d4 + 2) * ZPAD + r] = v.z;
        zs[(d4 + 3) * ZPAD + r] = v.w;
    }

    float zsqr[8];
    {
        float4 q0 = *(const float4*)(g_zsq + row0 + ty * 8);
        float4 q1 = *(const float4*)(g_zsq + row0 + ty * 8 + 4);
        zsqr[0] = q0.x; zsqr[1] = q0.y; zsqr[2] = q0.z; zsqr[3] = q0.w;
        zsqr[4] = q1.x; zsqr[5] = q1.y; zsqr[6] = q1.z; zsqr[7] = q1.w;
    }
    __syncthreads();

    float best[8];
    int   bidx[8];
#pragma unroll
    for (int i = 0; i < 8; i++) { best[i] = CUDART_INF_F; bidx[i] = 0; }

    const int c  = tid >> 1;          // codebook col within tile (0..127)
    const int dq = (tid & 1) * 4;     // chunk-local d offset (0 or 4)

    for (int kt = 0; kt < KCB; kt += BN) {
        float acc[8][8];
#pragma unroll
        for (int i = 0; i < 8; i++)
#pragma unroll
            for (int j = 0; j < 8; j++) acc[i][j] = 0.f;

        const float* src = cb + (size_t)(kt + c) * D + dq;
        float4 pre = *(const float4*)src;   // prefetch chunk 0
        int buf = 0;

        for (int dc = 0; dc < D; dc += 8) {
            float* eb = es + buf * SM_E;
            eb[(dq + 0) * ZPAD + c] = pre.x;
            eb[(dq + 1) * ZPAD + c] = pre.y;
            eb[(dq + 2) * ZPAD + c] = pre.z;
            eb[(dq + 3) * ZPAD + c] = pre.w;
            __syncthreads();
            if (dc + 8 < D) pre = *(const float4*)(src + dc + 8);

#pragma unroll
            for (int d = 0; d < 8; d++) {
                const float* zr = zs + (dc + d) * ZPAD + ty * 8;
                const float* er = eb + d * ZPAD + tx * 8;
                float4 a0 = *(const float4*)(zr);
                float4 a1 = *(const float4*)(zr + 4);
                float4 b0 = *(const float4*)(er);
                float4 b1 = *(const float4*)(er + 4);
                float a[8] = {a0.x, a0.y, a0.z, a0.w, a1.x, a1.y, a1.z, a1.w};
                float b[8] = {b0.x, b0.y, b0.z, b0.w, b1.x, b1.y, b1.z, b1.w};
#pragma unroll
                for (int i = 0; i < 8; i++)
#pragma unroll
                    for (int j = 0; j < 8; j++)
                        acc[i][j] = fmaf(a[i], b[j], acc[i][j]);
            }
            buf ^= 1;
        }

        // distances + running argmin (first-index tie-break: strict '<', ascending j/kt)
        float es8[8];
        {
            float4 e0 = *(const float4*)(g_esq + kt + tx * 8);
            float4 e1 = *(const float4*)(g_esq + kt + tx * 8 + 4);
            es8[0] = e0.x; es8[1] = e0.y; es8[2] = e0.z; es8[3] = e0.w;
            es8[4] = e1.x; es8[5] = e1.y; es8[6] = e1.z; es8[7] = e1.w;
        }
#pragma unroll
        for (int i = 0; i < 8; i++) {
#pragma unroll
            for (int j = 0; j < 8; j++) {
                float t    = zsqr[i] + es8[j];
                float dist = fmaf(-2.0f, acc[i][j], t);
                if (dist < best[i]) { best[i] = dist; bidx[i] = kt + tx * 8 + j; }
            }
        }
    }

    // Cross-tx argmin reduce (16-lane groups), explicit min-index tie-break
#pragma unroll
    for (int off = 8; off; off >>= 1) {
#pragma unroll
        for (int i = 0; i < 8; i++) {
            float ov = __shfl_down_sync(0xffffffffu, best[i], off, 16);
            int   oi = __shfl_down_sync(0xffffffffu, bidx[i], off, 16);
            if (ov < best[i] || (ov == best[i] && oi < bidx[i])) {
                best[i] = ov; bidx[i] = oi;
            }
        }
    }
    if (tx == 0) {
#pragma unroll
        for (int i = 0; i < 8; i++) {
            int r = row0 + ty * 8 + i;
            g_idx[r] = bidx[i];
            if (write_idxf) out_idxf[r] = (float)bidx[i];
        }
    }
}

// ---------------------------------------------------------------------------
// Kernel 3: gather z_q = codebook[idx] into out, accumulate sum((z_q - x)^2)
// ---------------------------------------------------------------------------
__global__ void vq_gather(const float* __restrict__ x, const float* __restrict__ cb,
                          float* __restrict__ out_zq)
{
    const int warp  = (blockIdx.x * blockDim.x + threadIdx.x) >> 5;
    const int lane  = threadIdx.x & 31;
    const int nwarp = (gridDim.x * blockDim.x) >> 5;
    float ls = 0.f;
    for (int r = warp; r < NROWS; r += nwarp) {
        const int idx = g_idx[r];
        const float* crow = cb + (size_t)idx * D;
        const float* xrow = x + (size_t)r * D;
        float* orow = out_zq + (size_t)r * D;
#pragma unroll
        for (int i = 0; i < 2; i++) {
            float4 v  = *(const float4*)(crow + lane * 8 + i * 4);
            float4 xv = *(const float4*)(xrow + lane * 8 + i * 4);
            *(float4*)(orow + lane * 8 + i * 4) = v;
            float dx = v.x - xv.x, dy = v.y - xv.y;
            float dz = v.z - xv.z, dw = v.w - xv.w;
            ls = fmaf(dx, dx, fmaf(dy, dy, fmaf(dz, dz, fmaf(dw, dw, ls))));
        }
    }
#pragma unroll
    for (int off = 16; off; off >>= 1) ls += __shfl_xor_sync(0xffffffffu, ls, off);
    __shared__ float ws[8];
    if (lane == 0) ws[threadIdx.x >> 5] = ls;
    __syncthreads();
    if (threadIdx.x == 0) {
        float s = 0.f;
        for (int i = 0; i < (int)(blockDim.x >> 5); i++) s += ws[i];
        atomicAdd(&g_loss, (double)s);
    }
}

__global__ void vq_final(float* out_loss)
{
    // loss = mean((zq-x)^2) + 0.25*mean((zq-x)^2) (stop_gradient is value-identity)
    *out_loss = (float)(1.25 * g_loss / ((double)NROWS * (double)D));
}

__global__ void vq_idx_int(int* __restrict__ out)
{
    int i = blockIdx.x * blockDim.x + threadIdx.x;
    if (i < NROWS) out[i] = g_idx[i];
}

// ---------------------------------------------------------------------------
extern "C" void kernel_launch(void* const* d_in, const int* in_sizes, int n_in,
                              void* d_out, int out_size)
{
    (void)in_sizes; (void)n_in;
    const float* x  = (const float*)d_in[0];
    const float* cb = (const float*)d_in[1];
    float* out = (float*)d_out;

    const long long ND = (long long)NROWS * D;
    const bool has_zq = (long long)out_size >= ND;
    const bool full   = (long long)out_size >= ND + 1 + NROWS;

    cudaFuncSetAttribute(vq_main, cudaFuncAttributeMaxDynamicSharedMemorySize,
                         SMEM_BYTES);

    vq_prep<<<144, 256>>>(x, cb);

    float* out_idxf = full ? (out + ND + 1) : nullptr;
    vq_main<<<NROWS / BM, 256, SMEM_BYTES>>>(x, cb, out_idxf, full ? 1 : 0);

    if (has_zq) {
        vq_gather<<<512, 256>>>(x, cb, out);
        if (full) vq_final<<<1, 1>>>(out + ND);
    } else if (out_size >= NROWS) {
        // fallback layout: indices-only output
        vq_idx_int<<<(NROWS + 255) / 256, 256>>>((int*)d_out);
    }
}

// round 2
// speedup vs baseline: 1.1453x; 1.1453x over previous
#include <cuda_runtime.h>
#include <math_constants.h>
#include <cstdint>

#define D     256
#define NROWS 32768
#define KCB   4096
#define BM    128
#define BN    128
#define ZS    132                 // z-tile row stride (floats), 528B: 16B-aligned, bank-staggered
#define ESTR  128                 // e-tile row stride (floats)
#define SM_Z  (D * ZS)            // 33792 floats
#define SM_E  (8 * ESTR)          // 1024 floats per buffer
#define SMEM_BYTES ((SM_Z + 2 * SM_E) * 4)   // 143360 B

typedef unsigned long long u64;

// Packed fp32x2 helpers (Blackwell FFMA2 — per-lane IEEE fp32, identical to scalar fmaf)
__device__ __forceinline__ u64 pack2(float lo, float hi) {
    u64 r; asm("mov.b64 %0, {%1, %2};" : "=l"(r) : "f"(lo), "f"(hi)); return r;
}
__device__ __forceinline__ void fma2(u64& acc, u64 a, u64 b) {
    asm("fma.rn.f32x2 %0, %1, %2, %0;" : "+l"(acc) : "l"(a), "l"(b));
}
__device__ __forceinline__ void unpack2(float& lo, float& hi, u64 v) {
    asm("mov.b64 {%0, %1}, %2;" : "=f"(lo), "=f"(hi) : "l"(v));
}

// Scratch (device globals: no allocations allowed in kernel_launch)
__device__ float  g_zsq[NROWS];
__device__ float  g_esq[KCB];
__device__ int    g_idx[NROWS];
__device__ double g_loss;

// ---------------------------------------------------------------------------
// Kernel 1: row norms ||z||^2 and ||e||^2, zero loss accum.
// ---------------------------------------------------------------------------
__global__ void vq_prep(const float* __restrict__ x, const float* __restrict__ cb)
{
    if (blockIdx.x == 0 && threadIdx.x == 0) g_loss = 0.0;
    const int warp  = (blockIdx.x * blockDim.x + threadIdx.x) >> 5;
    const int lane  = threadIdx.x & 31;
    const int nwarp = (gridDim.x * blockDim.x) >> 5;
    for (int r = warp; r < NROWS + KCB; r += nwarp) {
        const float* src = (r < NROWS) ? (x + (size_t)r * D)
                                       : (cb + (size_t)(r - NROWS) * D);
        float s = 0.f;
#pragma unroll
        for (int i = 0; i < 2; i++) {
            float4 v = *(const float4*)(src + lane * 8 + i * 4);
            s = fmaf(v.x, v.x, s); s = fmaf(v.y, v.y, s);
            s = fmaf(v.z, v.z, s); s = fmaf(v.w, v.w, s);
        }
#pragma unroll
        for (int off = 16; off; off >>= 1) s += __shfl_xor_sync(0xffffffffu, s, off);
        if (lane == 0) { if (r < NROWS) g_zsq[r] = s; else g_esq[r - NROWS] = s; }
    }
}

// ---------------------------------------------------------------------------
// Kernel 2: fused distance-GEMM + argmin, FFMA2 (fp32x2) inner loop.
// Block = 128 z rows (persistent, d-major smem) x full K loop in 128-entry tiles.
// Thread tile 8 rows x 8 cols; accumulators packed in row-pairs (4x8 u64).
// Per thread j-set: {tx*4..tx*4+3} U {64+tx*4..+3} -> two contiguous,
// conflict-free LDS.128 b-loads. a-loads are warp-broadcast (d-major).
// Distance mirrors reference rounding exactly:
//   t = fl(z_sq + e_sq);  dist = fl(t - 2*acc), first-index tie-break.
// ---------------------------------------------------------------------------
__global__ void __launch_bounds__(256, 1)
vq_main(const float* __restrict__ x, const float* __restrict__ cb,
        float* __restrict__ out_idxf, int write_idxf)
{
    extern __shared__ float sm[];
    float* zs = sm;           // [D][ZS]
    float* es = sm + SM_Z;    // [2][8][ESTR]

    const int tid  = threadIdx.x;
    const int tx   = tid & 15;
    const int ty   = tid >> 4;
    const int row0 = blockIdx.x * BM;

    // Load z tile, transposed to d-major
    for (int i = tid; i < BM * (D / 4); i += 256) {
        int r  = i >> 6;             // 0..127
        int d4 = (i & 63) << 2;      // 0,4,...,252
        float4 v = *(const float4*)(x + (size_t)(row0 + r) * D + d4);
        zs[(d4 + 0) * ZS + r] = v.x;
        zs[(d4 + 1) * ZS + r] = v.y;
        zs[(d4 + 2) * ZS + r] = v.z;
        zs[(d4 + 3) * ZS + r] = v.w;
    }

    float zsqr[8];
    {
        float4 q0 = *(const float4*)(g_zsq + row0 + ty * 8);
        float4 q1 = *(const float4*)(g_zsq + row0 + ty * 8 + 4);
        zsqr[0] = q0.x; zsqr[1] = q0.y; zsqr[2] = q0.z; zsqr[3] = q0.w;
        zsqr[4] = q1.x; zsqr[5] = q1.y; zsqr[6] = q1.z; zsqr[7] = q1.w;
    }
    __syncthreads();

    float best[8];
    int   bidx[8];
#pragma unroll
    for (int i = 0; i < 8; i++) { best[i] = CUDART_INF_F; bidx[i] = 0; }

    const int c  = tid >> 1;          // codebook col within tile (0..127)
    const int dq = (tid & 1) * 4;     // chunk-local d offset (0 or 4)

    for (int kt = 0; kt < KCB; kt += BN) {
        u64 acc2[4][8];
#pragma unroll
        for (int i = 0; i < 4; i++)
#pragma unroll
            for (int j = 0; j < 8; j++) acc2[i][j] = 0ULL;  // {0.f, 0.f}

        const float* src = cb + (size_t)(kt + c) * D + dq;
        float4 pre = *(const float4*)src;   // prefetch chunk 0
        int buf = 0;

        for (int dc = 0; dc < D; dc += 8) {
            float* eb = es + buf * SM_E;
            eb[(dq + 0) * ESTR + c] = pre.x;
            eb[(dq + 1) * ESTR + c] = pre.y;
            eb[(dq + 2) * ESTR + c] = pre.z;
            eb[(dq + 3) * ESTR + c] = pre.w;
            __syncthreads();
            if (dc + 8 < D) pre = *(const float4*)(src + dc + 8);

#pragma unroll
            for (int d = 0; d < 8; d++) {
                const float* zr = zs + (dc + d) * ZS + ty * 8;
                ulonglong2 av0 = *(const ulonglong2*)(zr);      // rows 0-3 (2 packed pairs)
                ulonglong2 av1 = *(const ulonglong2*)(zr + 4);  // rows 4-7
                u64 a2[4] = {av0.x, av0.y, av1.x, av1.y};

                const float* er = eb + d * ESTR + tx * 4;
                float4 b0 = *(const float4*)(er);        // j 0..3  (k = kt+tx*4+q)
                float4 b1 = *(const float4*)(er + 64);   // j 4..7  (k = kt+64+tx*4+q)
                u64 bb[8];
                bb[0] = pack2(b0.x, b0.x); bb[1] = pack2(b0.y, b0.y);
                bb[2] = pack2(b0.z, b0.z); bb[3] = pack2(b0.w, b0.w);
                bb[4] = pack2(b1.x, b1.x); bb[5] = pack2(b1.y, b1.y);
                bb[6] = pack2(b1.z, b1.z); bb[7] = pack2(b1.w, b1.w);

#pragma unroll
                for (int i = 0; i < 4; i++)
#pragma unroll
                    for (int j = 0; j < 8; j++)
                        fma2(acc2[i][j], a2[i], bb[j]);
            }
            buf ^= 1;
        }

        // distances + running argmin (first-index tie-break: strict '<', k ascending
        // within each thread's scan order)
        float es8[8];
        {
            float4 e0 = *(const float4*)(g_esq + kt + tx * 4);
            float4 e1 = *(const float4*)(g_esq + kt + 64 + tx * 4);
            es8[0] = e0.x; es8[1] = e0.y; es8[2] = e0.z; es8[3] = e0.w;
            es8[4] = e1.x; es8[5] = e1.y; es8[6] = e1.z; es8[7] = e1.w;
        }
#pragma unroll
        for (int i2 = 0; i2 < 4; i2++) {
#pragma unroll
            for (int j = 0; j < 8; j++) {
                const int kj = kt + ((j < 4) ? (tx * 4 + j) : (64 + tx * 4 + (j - 4)));
                float alo, ahi;
                unpack2(alo, ahi, acc2[i2][j]);
                float tlo = zsqr[2 * i2 + 0] + es8[j];
                float thi = zsqr[2 * i2 + 1] + es8[j];
                float dlo = fmaf(-2.0f, alo, tlo);
                float dhi = fmaf(-2.0f, ahi, thi);
                if (dlo < best[2 * i2 + 0]) { best[2 * i2 + 0] = dlo; bidx[2 * i2 + 0] = kj; }
                if (dhi < best[2 * i2 + 1]) { best[2 * i2 + 1] = dhi; bidx[2 * i2 + 1] = kj; }
            }
        }
    }

    // Cross-tx argmin reduce (16-lane groups), explicit min-index tie-break.
    // (thread scan order is k-ascending, so equal-valued duplicates within a
    //  thread already hold the smallest k; cross-thread ties resolved by index)
#pragma unroll
    for (int off = 8; off; off >>= 1) {
#pragma unroll
        for (int i = 0; i < 8; i++) {
            float ov = __shfl_down_sync(0xffffffffu, best[i], off, 16);
            int   oi = __shfl_down_sync(0xffffffffu, bidx[i], off, 16);
            if (ov < best[i] || (ov == best[i] && oi < bidx[i])) {
                best[i] = ov; bidx[i] = oi;
            }
        }
    }
    if (tx == 0) {
#pragma unroll
        for (int i = 0; i < 8; i++) {
            int r = row0 + ty * 8 + i;
            g_idx[r] = bidx[i];
            if (write_idxf) out_idxf[r] = (float)bidx[i];
        }
    }
}

// ---------------------------------------------------------------------------
// Kernel 3: gather z_q = codebook[idx] into out, accumulate sum((z_q - x)^2)
// ---------------------------------------------------------------------------
__global__ void vq_gather(const float* __restrict__ x, const float* __restrict__ cb,
                          float* __restrict__ out_zq)
{
    const int warp  = (blockIdx.x * blockDim.x + threadIdx.x) >> 5;
    const int lane  = threadIdx.x & 31;
    const int nwarp = (gridDim.x * blockDim.x) >> 5;
    float ls = 0.f;
    for (int r = warp; r < NROWS; r += nwarp) {
        const int idx = g_idx[r];
        const float* crow = cb + (size_t)idx * D;
        const float* xrow = x + (size_t)r * D;
        float* orow = out_zq + (size_t)r * D;
#pragma unroll
        for (int i = 0; i < 2; i++) {
            float4 v  = *(const float4*)(crow + lane * 8 + i * 4);
            float4 xv = *(const float4*)(xrow + lane * 8 + i * 4);
            *(float4*)(orow + lane * 8 + i * 4) = v;
            float dx = v.x - xv.x, dy = v.y - xv.y;
            float dz = v.z - xv.z, dw = v.w - xv.w;
            ls = fmaf(dx, dx, fmaf(dy, dy, fmaf(dz, dz, fmaf(dw, dw, ls))));
        }
    }
#pragma unroll
    for (int off = 16; off; off >>= 1) ls += __shfl_xor_sync(0xffffffffu, ls, off);
    __shared__ float ws[8];
    if (lane == 0) ws[threadIdx.x >> 5] = ls;
    __syncthreads();
    if (threadIdx.x == 0) {
        float s = 0.f;
        for (int i = 0; i < (int)(blockDim.x >> 5); i++) s += ws[i];
        atomicAdd(&g_loss, (double)s);
    }
}

__global__ void vq_final(float* out_loss)
{
    *out_loss = (float)(1.25 * g_loss / ((double)NROWS * (double)D));
}

__global__ void vq_idx_int(int* __restrict__ out)
{
    int i = blockIdx.x * blockDim.x + threadIdx.x;
    if (i < NROWS) out[i] = g_idx[i];
}

// ---------------------------------------------------------------------------
extern "C" void kernel_launch(void* const* d_in, const int* in_sizes, int n_in,
                              void* d_out, int out_size)
{
    (void)in_sizes; (void)n_in;
    const float* x  = (const float*)d_in[0];
    const float* cb = (const float*)d_in[1];
    float* out = (float*)d_out;

    const long long ND = (long long)NROWS * D;
    const bool has_zq = (long long)out_size >= ND;
    const bool full   = (long long)out_size >= ND + 1 + NROWS;

    cudaFuncSetAttribute(vq_main, cudaFuncAttributeMaxDynamicSharedMemorySize,
                         SMEM_BYTES);

    vq_prep<<<144, 256>>>(x, cb);

    float* out_idxf = full ? (out + ND + 1) : nullptr;
    vq_main<<<NROWS / BM, 256, SMEM_BYTES>>>(x, cb, out_idxf, full ? 1 : 0);

    if (has_zq) {
        vq_gather<<<512, 256>>>(x, cb, out);
        if (full) vq_final<<<1, 1>>>(out + ND);
    } else if (out_size >= NROWS) {
        vq_idx_int<<<(NROWS + 255) / 256, 256>>>((int*)d_out);
    }
}

// round 5
// speedup vs baseline: 3.4726x; 3.0322x over previous
#include <cuda_runtime.h>
#include <cuda_bf16.h>
#include <math_constants.h>
#include <cstdint>

#define D     256
#define NROWS 32768
#define KCB   4096

#define MT      256                 // rows per CTA
#define GRID_M  (NROWS / MT)        // 128 CTAs = single wave
#define NCH     64                  // codebook entries per chunk
#define CHUNKS  (KCB / NCH)         // 64

// smem byte offsets
#define SA_OFF   0                  // A: 32 kb x 256 m x 16B = 131072
#define SB_OFF   131072             // B: 2 bufs x (32 kb x 64 n x 16B = 32768)
#define SESQ_OFF 196608             // esq: 4096 floats = 16384
#define SMEM_BYTES 212992

// ---- device scratch ----
__device__ __nv_bfloat16 g_zh[NROWS * D];     // 16MB
__device__ __nv_bfloat16 g_cbh[KCB * D];      // 2MB
__device__ float  g_zsq[NROWS];
__device__ float  g_esq[KCB];
__device__ int    g_cand16[NROWS * 16];       // 2MB
__device__ int    g_idx[NROWS];
__device__ double g_loss;

// ---- PTX helpers (all sm_80-compatible; no 'a'-suffix features) ----
__device__ __forceinline__ uint32_t smem_u32(const void* p) {
    uint32_t a;
    asm("{ .reg .u64 t; cvta.to.shared.u64 t, %1; cvt.u32.u64 %0, t; }" : "=r"(a) : "l"(p));
    return a;
}
__device__ __forceinline__ void cpa16(uint32_t dst, const void* src) {
    asm volatile("cp.async.cg.shared.global [%0], [%1], 16;" :: "r"(dst), "l"(src));
}
#define CP_COMMIT() asm volatile("cp.async.commit_group;" ::: "memory")
#define CP_WAIT0()  asm volatile("cp.async.wait_group 0;" ::: "memory")

__device__ __forceinline__ void ldsm_x4(uint32_t* r, uint32_t addr) {
    asm volatile("ldmatrix.sync.aligned.m8n8.x4.shared.b16 {%0,%1,%2,%3}, [%4];"
                 : "=r"(r[0]), "=r"(r[1]), "=r"(r[2]), "=r"(r[3]) : "r"(addr));
}
__device__ __forceinline__ void ldsm_x2(uint32_t* r, uint32_t addr) {
    asm volatile("ldmatrix.sync.aligned.m8n8.x2.shared.b16 {%0,%1}, [%2];"
                 : "=r"(r[0]), "=r"(r[1]) : "r"(addr));
}
__device__ __forceinline__ void mma_bf16(float* c, const uint32_t* a, const uint32_t* b) {
    asm volatile("mma.sync.aligned.m16n8k16.row.col.f32.bf16.bf16.f32 "
                 "{%0,%1,%2,%3}, {%4,%5,%6,%7}, {%8,%9}, {%0,%1,%2,%3};"
                 : "+f"(c[0]), "+f"(c[1]), "+f"(c[2]), "+f"(c[3])
                 : "r"(a[0]), "r"(a[1]), "r"(a[2]), "r"(a[3]), "r"(b[0]), "r"(b[1]));
}
__device__ __forceinline__ uint32_t bf16x2(float lo, float hi) {
    uint32_t r; asm("cvt.rn.bf16x2.f32 %0, %1, %2;" : "=r"(r) : "f"(hi), "f"(lo));
    return r;
}

// ---------------------------------------------------------------------------
// Kernel 1: bf16 conversion of x and codebook + fp32 row norms.
// ---------------------------------------------------------------------------
__global__ void vq_prep(const float* __restrict__ x, const float* __restrict__ cb)
{
    if (blockIdx.x == 0 && threadIdx.x == 0) g_loss = 0.0;
    const int warp  = (blockIdx.x * blockDim.x + threadIdx.x) >> 5;
    const int lane  = threadIdx.x & 31;
    const int nwarp = (gridDim.x * blockDim.x) >> 5;
    for (int r = warp; r < NROWS + KCB; r += nwarp) {
        const bool isz = r < NROWS;
        const int  rr  = isz ? r : (r - NROWS);
        const float* src = (isz ? x : cb) + (size_t)rr * D;
        __nv_bfloat16* dst = (isz ? g_zh : g_cbh) + (size_t)rr * D;
        float s = 0.f;
#pragma unroll
        for (int i = 0; i < 2; i++) {
            const int o = lane * 8 + i * 4;
            float4 v = *(const float4*)(src + o);
            s = fmaf(v.x, v.x, s); s = fmaf(v.y, v.y, s);
            s = fmaf(v.z, v.z, s); s = fmaf(v.w, v.w, s);
            uint2 p;
            p.x = bf16x2(v.x, v.y);
            p.y = bf16x2(v.z, v.w);
            *(uint2*)(dst + o) = p;
        }
#pragma unroll
        for (int off = 16; off; off >>= 1) s += __shfl_xor_sync(0xffffffffu, s, off);
        if (lane == 0) { if (isz) g_zsq[rr] = s; else g_esq[rr] = s; }
    }
}

// ---------------------------------------------------------------------------
// Kernel 2: bf16 mma.sync distance GEMM + per-thread top-2 candidates.
// A resident in smem (swizzled [kb][m] 16B cells); B streamed 64 entries/chunk,
// double-buffered via cp.async. Warp grid 4m x 2n; warp tile 64m x 32n.
// Ranking key: esq_j - 2*dot_j (zsq constant per row). 16 cand/row emitted.
// ---------------------------------------------------------------------------
__global__ void __launch_bounds__(256, 1) vq_main_mma()
{
    extern __shared__ char sm[];
    float* s_esq = (float*)(sm + SESQ_OFF);
    const uint32_t smb = smem_u32(sm);

    const int tid  = threadIdx.x;
    const int wid  = tid >> 5;
    const int lane = tid & 31;
    const int g    = lane >> 2;          // group id (row within 8)
    const int tig  = lane & 3;
    const int mw   = wid & 3;            // warp m index (0..3)
    const int nw   = wid >> 2;           // warp n index (0..1)
    const int row0 = blockIdx.x * MT;

    // ---- prologue: A tile (8192 cells) + esq via cp.async / plain ----
    for (int idx = tid; idx < 8192; idx += 256) {
        const int kb = idx & 31, m = idx >> 5;
        const uint32_t dst = smb + SA_OFF + (kb << 12) + (((m ^ (kb & 7))) << 4);
        cpa16(dst, g_zh + (size_t)(row0 + m) * D + kb * 8);
    }
    // B chunk 0
    for (int idx = tid; idx < 2048; idx += 256) {
        const int kb = idx & 31, n = idx >> 5;
        const uint32_t dst = smb + SB_OFF + (kb << 10) + (((n ^ (kb & 7))) << 4);
        cpa16(dst, g_cbh + (size_t)n * D + kb * 8);
    }
    CP_COMMIT();
    for (int i = tid; i < KCB / 4; i += 256)
        ((float4*)s_esq)[i] = ((const float4*)g_esq)[i];
    CP_WAIT0();
    __syncthreads();

    // ldmatrix address components
    const int jm = lane >> 3;                        // 0..3 (A matrix id)
    const int m_base = mw * 64 + ((jm & 1) << 3) + (lane & 7);
    const int kbo_m  = jm >> 1;                      // 0/1
    const int jb = (lane >> 3) & 1;                  // B matrix id (lanes 0-15 used)
    const int n_base = nw * 32 + (lane & 7);

    float b1[8], b2[8]; int i1[8], i2[8];
#pragma unroll
    for (int s = 0; s < 8; s++) { b1[s] = CUDART_INF_F; b2[s] = CUDART_INF_F; i1[s] = 0; i2[s] = 0; }

    for (int c = 0; c < CHUNKS; c++) {
        const uint32_t bufB = smb + SB_OFF + (uint32_t)(c & 1) * 32768;
        // issue next chunk's loads into the other buffer
        if (c + 1 < CHUNKS) {
            const uint32_t nb = smb + SB_OFF + (uint32_t)((c + 1) & 1) * 32768;
            const int n0n = (c + 1) * NCH;
            for (int idx = tid; idx < 2048; idx += 256) {
                const int kb = idx & 31, n = idx >> 5;
                cpa16(nb + (kb << 10) + (((n ^ (kb & 7))) << 4),
                      g_cbh + (size_t)(n0n + n) * D + kb * 8);
            }
        }
        CP_COMMIT();

        float acc[4][4][4];
#pragma unroll
        for (int mi = 0; mi < 4; mi++)
#pragma unroll
            for (int ni = 0; ni < 4; ni++)
#pragma unroll
                for (int q = 0; q < 4; q++) acc[mi][ni][q] = 0.f;

#pragma unroll 4
        for (int k2 = 0; k2 < 16; k2++) {
            uint32_t af[4][4], bf[4][2];
            const int kbm = 2 * k2 + kbo_m;
            const int kbb = 2 * k2 + jb;
#pragma unroll
            for (int mi = 0; mi < 4; mi++) {
                const int m = m_base + mi * 16;
                ldsm_x4(af[mi], smb + SA_OFF + (kbm << 12) + (((m ^ (kbm & 7))) << 4));
            }
#pragma unroll
            for (int ni = 0; ni < 4; ni++) {
                const int n = n_base + ni * 8;
                ldsm_x2(bf[ni], bufB + (kbb << 10) + (((n ^ (kbb & 7))) << 4));
            }
#pragma unroll
            for (int mi = 0; mi < 4; mi++)
#pragma unroll
                for (int ni = 0; ni < 4; ni++)
                    mma_bf16(acc[mi][ni], af[mi], bf[ni]);
        }

        // epilogue: fold 64 values into per-slot running top-2
        const int n0 = c * NCH;
#pragma unroll
        for (int ni = 0; ni < 4; ni++) {
            const int c0 = n0 + nw * 32 + ni * 8 + 2 * tig;
            const float e0 = s_esq[c0];
            const float e1 = s_esq[c0 + 1];
#pragma unroll
            for (int mi = 0; mi < 4; mi++) {
#pragma unroll
                for (int h = 0; h < 2; h++) {
                    const int s = mi * 2 + h;
                    float v0 = fmaf(-2.0f, acc[mi][ni][2 * h + 0], e0);
                    float v1 = fmaf(-2.0f, acc[mi][ni][2 * h + 1], e1);
                    if (v0 < b1[s]) { b2[s] = b1[s]; i2[s] = i1[s]; b1[s] = v0; i1[s] = c0; }
                    else if (v0 < b2[s]) { b2[s] = v0; i2[s] = c0; }
                    if (v1 < b1[s]) { b2[s] = b1[s]; i2[s] = i1[s]; b1[s] = v1; i1[s] = c0 + 1; }
                    else if (v1 < b2[s]) { b2[s] = v1; i2[s] = c0 + 1; }
                }
            }
        }

        CP_WAIT0();
        __syncthreads();
    }

    // emit 16 candidates per row (8 threads x 2 each), no merge needed
#pragma unroll
    for (int mi = 0; mi < 4; mi++)
#pragma unroll
        for (int h = 0; h < 2; h++) {
            const int s = mi * 2 + h;
            const int row = row0 + mw * 64 + mi * 16 + h * 8 + g;
            const int base = row * 16 + nw * 8 + tig * 2;
            g_cand16[base]     = i1[s];
            g_cand16[base + 1] = i2[s];
        }
}

// ---------------------------------------------------------------------------
// Kernel 3: exact fp32 re-rank of 16 candidates/row (reference rounding,
// min-index tie-break) — bitwise-equivalent to the R1-proven scalar path.
// ---------------------------------------------------------------------------
__global__ void vq_rerank(const float* __restrict__ x, const float* __restrict__ cb)
{
    const int warp  = (blockIdx.x * blockDim.x + threadIdx.x) >> 5;
    const int lane  = threadIdx.x & 31;
    const int nwarp = (gridDim.x * blockDim.x) >> 5;
    for (int r = warp; r < NROWS; r += nwarp) {
        const float* xr = x + (size_t)r * D;
        const float4 xa = *(const float4*)(xr + lane * 8);
        const float4 xb = *(const float4*)(xr + lane * 8 + 4);
        const float zq = g_zsq[r];
        float bb = CUDART_INF_F; int bi = 0x7fffffff;
#pragma unroll 4
        for (int cI = 0; cI < 16; cI++) {
            const int k = g_cand16[r * 16 + cI];
            const float* er = cb + (size_t)k * D;
            float4 ea = *(const float4*)(er + lane * 8);
            float4 eb = *(const float4*)(er + lane * 8 + 4);
            float p = 0.f;
            p = fmaf(xa.x, ea.x, p); p = fmaf(xa.y, ea.y, p);
            p = fmaf(xa.z, ea.z, p); p = fmaf(xa.w, ea.w, p);
            p = fmaf(xb.x, eb.x, p); p = fmaf(xb.y, eb.y, p);
            p = fmaf(xb.z, eb.z, p); p = fmaf(xb.w, eb.w, p);
#pragma unroll
            for (int off = 16; off; off >>= 1) p += __shfl_xor_sync(0xffffffffu, p, off);
            const float t  = zq + g_esq[k];
            const float dd = fmaf(-2.0f, p, t);
            if (dd < bb || (dd == bb && k < bi)) { bb = dd; bi = k; }
        }
        if (lane == 0) g_idx[r] = bi;
    }
}

// ---------------------------------------------------------------------------
// Kernel 4: gather z_q, loss accumulation, index write-out
// ---------------------------------------------------------------------------
__global__ void vq_gather(const float* __restrict__ x, const float* __restrict__ cb,
                          float* __restrict__ out_zq, float* __restrict__ out_idxf,
                          int write_idxf)
{
    const int warp  = (blockIdx.x * blockDim.x + threadIdx.x) >> 5;
    const int lane  = threadIdx.x & 31;
    const int nwarp = (gridDim.x * blockDim.x) >> 5;
    float ls = 0.f;
    for (int r = warp; r < NROWS; r += nwarp) {
        const int idx = g_idx[r];
        const float* crow = cb + (size_t)idx * D;
        const float* xrow = x + (size_t)r * D;
        float* orow = out_zq + (size_t)r * D;
        if (write_idxf && lane == 0) out_idxf[r] = (float)idx;
#pragma unroll
        for (int i = 0; i < 2; i++) {
            float4 v  = *(const float4*)(crow + lane * 8 + i * 4);
            float4 xv = *(const float4*)(xrow + lane * 8 + i * 4);
            *(float4*)(orow + lane * 8 + i * 4) = v;
            float dx = v.x - xv.x, dy = v.y - xv.y;
            float dz = v.z - xv.z, dw = v.w - xv.w;
            ls = fmaf(dx, dx, fmaf(dy, dy, fmaf(dz, dz, fmaf(dw, dw, ls))));
        }
    }
#pragma unroll
    for (int off = 16; off; off >>= 1) ls += __shfl_xor_sync(0xffffffffu, ls, off);
    __shared__ float ws[8];
    if (lane == 0) ws[threadIdx.x >> 5] = ls;
    __syncthreads();
    if (threadIdx.x == 0) {
        float s = 0.f;
        for (int i = 0; i < (int)(blockDim.x >> 5); i++) s += ws[i];
        atomicAdd(&g_loss, (double)s);
    }
}

__global__ void vq_final(float* out_loss)
{
    *out_loss = (float)(1.25 * g_loss / ((double)NROWS * (double)D));
}

__global__ void vq_idx_int(int* __restrict__ out)
{
    int i = blockIdx.x * blockDim.x + threadIdx.x;
    if (i < NROWS) out[i] = g_idx[i];
}

// ---------------------------------------------------------------------------
extern "C" void kernel_launch(void* const* d_in, const int* in_sizes, int n_in,
                              void* d_out, int out_size)
{
    (void)in_sizes; (void)n_in;
    const float* x  = (const float*)d_in[0];
    const float* cb = (const float*)d_in[1];
    float* out = (float*)d_out;

    const long long ND = (long long)NROWS * D;
    const bool has_zq = (long long)out_size >= ND;
    const bool full   = (long long)out_size >= ND + 1 + NROWS;

    cudaFuncSetAttribute(vq_main_mma, cudaFuncAttributeMaxDynamicSharedMemorySize,
                         SMEM_BYTES);

    vq_prep<<<288, 256>>>(x, cb);
    vq_main_mma<<<GRID_M, 256, SMEM_BYTES>>>();
    vq_rerank<<<256, 256>>>(x, cb);

    if (has_zq) {
        float* out_idxf = full ? (out + ND + 1) : nullptr;
        vq_gather<<<512, 256>>>(x, cb, out, out_idxf, full ? 1 : 0);
        if (full) vq_final<<<1, 1>>>(out + ND);
    } else if (out_size >= NROWS) {
        vq_idx_int<<<(NROWS + 255) / 256, 256>>>((int*)d_out);
    }
}